// round 1
// baseline (speedup 1.0000x reference)
#include <cuda_runtime.h>
#include <cuda_bf16.h>

// =====================================================================
// ATQCNN: 9-wire circuit, but wires 7,8 stay |0> (only CNOT controls on
// them -> identity). Effective 128-dim linear map U (wires 0..6).
//   Y[b]   = U @ x[b]                       (U orthogonal, fixed per call)
//   q[b,k] = sum_{m & 3 == k} Y[b,m]^2      (wire5->bit1, wire6->bit0 of m)
//   probs  = q / sum_k q  (= q / ||x||^2 by orthogonality)
//   out    = softmax(probs)
// Kernel 1 builds U (transposed, [i][m]) by simulating 128 basis states.
// Kernel 2 is a small fp32 GEMM with squared-sum + softmax epilogue.
// =====================================================================

__device__ float g_AT[128 * 128];   // g_AT[i*128 + m] = <m| U |i>

// ----------------------------- Kernel 1 ------------------------------
// 128 blocks (one basis state each) x 64 threads (one amp-pair each).
__global__ void build_A_kernel(const float* __restrict__ QC1,
                               const float* __restrict__ QC2,
                               const float* __restrict__ QC3,
                               const float* __restrict__ QP1,
                               const float* __restrict__ QP2,
                               const float* __restrict__ QP3,
                               const float* __restrict__ QF) {
    __shared__ float s[128];
    __shared__ float2 cs[46];   // (cos(th/2), sin(th/2)) per distinct angle

    const int t = threadIdx.x;       // 0..63
    const int basis = blockIdx.x;    // 0..127

    // Precompute all distinct half-angle (cos, sin) pairs once.
    if (t < 46) {
        float ang;
        if      (t < 12) ang = QC1[t];
        else if (t < 24) ang = QC2[t - 12];
        else if (t < 36) ang = QC3[t - 24];
        else if (t == 36) ang =  QP1[0];
        else if (t == 37) ang =  QP1[1];
        else if (t == 38) ang = -QP1[1];
        else if (t == 39) ang =  QP2[0];
        else if (t == 40) ang =  QP2[1];
        else if (t == 41) ang = -QP2[1];
        else if (t == 42) ang =  QP3[0];
        else if (t == 43) ang =  QP3[1];
        else if (t == 44) ang = -QP3[1];
        else              ang = QF[0] + QF[1] + QF[2] + QF[3]; // RY angles add
        float sn, c;
        sincosf(0.5f * ang, &sn, &c);
        cs[t] = make_float2(c, sn);
    }

    // Basis state |basis> on wires 0..6.
    s[t]      = (t == basis)      ? 1.0f : 0.0f;
    s[t + 64] = (t + 64 == basis) ? 1.0f : 0.0f;

    // RY(w, theta): pairs differ in bit (6-w). Each thread owns one pair.
    auto RY = [&](int w, int aidx) {
        __syncthreads();
        const float2 v = cs[aidx];
        const int sh = 6 - w;
        const int i0 = ((t >> sh) << (sh + 1)) | (t & ((1 << sh) - 1));
        const int i1 = i0 | (1 << sh);
        const float a = s[i0], b = s[i1];
        s[i0] = v.x * a - v.y * b;
        s[i1] = v.y * a + v.x * b;
    };
    // CNOT(c, tg): swap target bit where control bit == 1.
    auto CNOT = [&](int c, int tg) {
        __syncthreads();
        const int bc = 6 - c, bt = 6 - tg;
        const int i0 = ((t >> bt) << (bt + 1)) | (t & ((1 << bt) - 1));
        const int i1 = i0 | (1 << bt);
        if ((i0 >> bc) & 1) {
            const float tmp = s[i0]; s[i0] = s[i1]; s[i1] = tmp;
        }
    };

    // conv block 1
    for (int i = 0; i < 7; ++i)
        for (int q = 0; q < 6; ++q) {
            RY(i, 2 * q);
            RY((i + 1) % 7, 2 * q + 1);
            CNOT(i, (i + 1) % 7);
        }
    // pool 1
    for (int i = 0; i < 3; ++i) {
        RY(i, 36); RY(i + 3, 37); CNOT(i, i + 3); RY(i + 3, 38);
    }
    // conv block 2
    for (int i = 3; i < 7; ++i) {
        if (i != 6)
            for (int q = 0; q < 6; ++q) {
                RY(i, 12 + 2 * q); RY(i + 1, 13 + 2 * q); CNOT(i, i + 1);
            }
        else
            for (int q = 0; q < 6; ++q) {
                RY(6, 12 + 2 * q); RY(3, 13 + 2 * q); CNOT(6, 0);
            }
    }
    // pool 2
    for (int i = 3; i < 5; ++i) {
        RY(i, 39); RY(i + 2, 40); CNOT(i, i + 2); RY(i + 2, 41);
    }
    // conv block 3 (reference bug preserved: CNOT(4,5))
    for (int q = 0; q < 6; ++q) {
        RY(5, 24 + 2 * q); RY(6, 25 + 2 * q); CNOT(4, 5);
    }
    // pool 3 (reference bug preserved: CNOT(4,6))
    RY(5, 42); RY(6, 43); CNOT(4, 6); RY(6, 44);
    // final block: 4x RY(5) fused; CNOT(7,5)/CNOT(8,6) are identity (ctrl |0>)
    RY(5, 45); CNOT(5, 6); CNOT(6, 5);

    __syncthreads();
    g_AT[basis * 128 + t]      = s[t];
    g_AT[basis * 128 + t + 64] = s[t + 64];
}

// ----------------------------- Kernel 2 ------------------------------
// 128 blocks x 256 threads. Block = 32 batches. Warp = 4 batches.
// Lane owns output rows m = 4*lane .. 4*lane+3 (one full k-group: k = m&3).
__device__ __forceinline__ void fma4(float4& acc, float xs, const float4& a) {
    acc.x = fmaf(xs, a.x, acc.x);
    acc.y = fmaf(xs, a.y, acc.y);
    acc.z = fmaf(xs, a.z, acc.z);
    acc.w = fmaf(xs, a.w, acc.w);
}

__global__ __launch_bounds__(256) void qcnn_apply_kernel(
        const float* __restrict__ X, float* __restrict__ out) {
    extern __shared__ float sm[];
    float4* As4 = reinterpret_cast<float4*>(sm);            // 16384 floats [i][m]
    float4* Xs4 = reinterpret_cast<float4*>(sm + 16384);    // 32*128 floats

    const int tid  = threadIdx.x;
    const int warp = tid >> 5;
    const int lane = tid & 31;
    const int bbase = blockIdx.x * 32;

    // Stage A^T and the X tile into shared memory (coalesced float4).
    const float4* gA4 = reinterpret_cast<const float4*>(g_AT);
    for (int k = tid; k < 4096; k += 256) As4[k] = gA4[k];
    const float4* gX4 = reinterpret_cast<const float4*>(X + (size_t)bbase * 128);
    for (int k = tid; k < 1024; k += 256) Xs4[k] = gX4[k];
    __syncthreads();

    const int b0 = warp * 4;              // local batch base for this warp
    const float4* Xw = Xs4 + b0 * 32;

    float4 acc[4] = {{0,0,0,0},{0,0,0,0},{0,0,0,0},{0,0,0,0}};

    #pragma unroll 8
    for (int i4 = 0; i4 < 32; ++i4) {
        // A rows for 4 consecutive i, this lane's 4 output columns.
        // Lanes cover a contiguous 512B row -> conflict-free LDS.128.
        const float4 a0 = As4[i4 * 128 +       lane];
        const float4 a1 = As4[i4 * 128 +  32 + lane];
        const float4 a2 = As4[i4 * 128 +  64 + lane];
        const float4 a3 = As4[i4 * 128 +  96 + lane];
        #pragma unroll
        for (int g = 0; g < 4; ++g) {
            const float4 xv = Xw[g * 32 + i4];   // uniform address: broadcast
            fma4(acc[g], xv.x, a0);
            fma4(acc[g], xv.y, a1);
            fma4(acc[g], xv.z, a2);
            fma4(acc[g], xv.w, a3);
        }
    }

    // Epilogue: per batch, q_k = sum over lanes of acc[g].comp_k^2,
    // probs = q / sum(q), softmax, one float4 store.
    #pragma unroll
    for (int g = 0; g < 4; ++g) {
        float q0 = acc[g].x * acc[g].x;
        float q1 = acc[g].y * acc[g].y;
        float q2 = acc[g].z * acc[g].z;
        float q3 = acc[g].w * acc[g].w;
        #pragma unroll
        for (int off = 16; off; off >>= 1) {
            q0 += __shfl_xor_sync(0xffffffffu, q0, off);
            q1 += __shfl_xor_sync(0xffffffffu, q1, off);
            q2 += __shfl_xor_sync(0xffffffffu, q2, off);
            q3 += __shfl_xor_sync(0xffffffffu, q3, off);
        }
        if (lane == 0) {
            const float S = q0 + q1 + q2 + q3;   // == ||x||^2 (U orthogonal)
            const float inv_s = 1.0f / S;
            const float p0 = q0 * inv_s, p1 = q1 * inv_s;
            const float p2 = q2 * inv_s, p3 = q3 * inv_s;
            const float mx = fmaxf(fmaxf(p0, p1), fmaxf(p2, p3));
            const float e0 = expf(p0 - mx), e1 = expf(p1 - mx);
            const float e2 = expf(p2 - mx), e3 = expf(p3 - mx);
            const float inv = 1.0f / (e0 + e1 + e2 + e3);
            const int b = bbase + b0 + g;
            reinterpret_cast<float4*>(out)[b] =
                make_float4(e0 * inv, e1 * inv, e2 * inv, e3 * inv);
        }
    }
}

// ----------------------------- launch --------------------------------
extern "C" void kernel_launch(void* const* d_in, const int* in_sizes, int n_in,
                              void* d_out, int out_size) {
    const float* x   = (const float*)d_in[0];
    const float* QC1 = (const float*)d_in[1];
    const float* QC2 = (const float*)d_in[2];
    const float* QC3 = (const float*)d_in[3];
    const float* QP1 = (const float*)d_in[4];
    const float* QP2 = (const float*)d_in[5];
    const float* QP3 = (const float*)d_in[6];
    const float* QF  = (const float*)d_in[7];

    const int B = in_sizes[0] / 128;

    build_A_kernel<<<128, 64>>>(QC1, QC2, QC3, QP1, QP2, QP3, QF);

    const int smem_bytes = (128 * 128 + 32 * 128) * sizeof(float);  // 80 KB
    cudaFuncSetAttribute(qcnn_apply_kernel,
                         cudaFuncAttributeMaxDynamicSharedMemorySize, smem_bytes);
    qcnn_apply_kernel<<<B / 32, 256, smem_bytes>>>(x, (float*)d_out);
}

// round 2
// speedup vs baseline: 1.5854x; 1.5854x over previous
#include <cuda_runtime.h>
#include <cuda_bf16.h>

// =====================================================================
// ATQCNN factorization:
//   U = fixed 128x128 orthogonal circuit matrix (wires 0..6; 7,8 inert)
//   Y[b] = U x[b];  q[b,k] = sum_{m&3==k} Y[b,m]^2;  out = softmax(q/sum q)
// Kernel 1: warp-per-basis register simulation (shfl, no barriers).
// Kernel 2: 4096x128x128 fp32 GEMM w/ squared-sum + softmax epilogue.
// =====================================================================

__device__ float g_AT[128 * 128];   // g_AT[i*128 + m] = <m| U |i>

// --------------------- gate primitives (register sim) -----------------
// Amp index m (7 bits): bits[6:2] = lane, bits[1:0] = register r.
// Bit position of wire w is P = 6 - w.

template<int P>
__device__ __forceinline__ void ry_p(float a[4], float c, float s, int lane) {
    if constexpr (P == 0) {                 // wire 6: pairs (a0,a1),(a2,a3)
        float n0 = c * a[0] - s * a[1];
        float n1 = fmaf(s, a[0], c * a[1]);
        float n2 = c * a[2] - s * a[3];
        float n3 = fmaf(s, a[2], c * a[3]);
        a[0] = n0; a[1] = n1; a[2] = n2; a[3] = n3;
    } else if constexpr (P == 1) {          // wire 5: pairs (a0,a2),(a1,a3)
        float n0 = c * a[0] - s * a[2];
        float n2 = fmaf(s, a[0], c * a[2]);
        float n1 = c * a[1] - s * a[3];
        float n3 = fmaf(s, a[1], c * a[3]);
        a[0] = n0; a[1] = n1; a[2] = n2; a[3] = n3;
    } else {                                // cross-lane wire
        constexpr int M = 1 << (P - 2);
        const float sgn = (lane & M) ? s : -s;
        #pragma unroll
        for (int r = 0; r < 4; ++r) {
            float pr = __shfl_xor_sync(0xffffffffu, a[r], M);
            a[r] = fmaf(sgn, pr, c * a[r]);
        }
    }
}

template<int W>
__device__ __forceinline__ void ry_w(float a[4], float2 cs, int lane) {
    ry_p<6 - W>(a, cs.x, cs.y, lane);
}

template<int PC, int PT>
__device__ __forceinline__ void cnot_p(float a[4], int lane) {
    if constexpr (PT >= 2) {                // target is a lane bit
        constexpr int MT = 1 << (PT - 2);
        if constexpr (PC >= 2) {            // control is a lane bit
            constexpr int MC = 1 << (PC - 2);
            const bool ctl = (lane & MC) != 0;
            #pragma unroll
            for (int r = 0; r < 4; ++r) {
                float pr = __shfl_xor_sync(0xffffffffu, a[r], MT);
                a[r] = ctl ? pr : a[r];
            }
        } else {                            // control in-register bit PC
            #pragma unroll
            for (int r = 0; r < 4; ++r) {
                if ((r >> PC) & 1) {        // compile-time after unroll
                    a[r] = __shfl_xor_sync(0xffffffffu, a[r], MT);
                }
            }
        }
    } else {                                // target in-register
        if constexpr (PC >= 2) {            // control is a lane bit
            constexpr int MC = 1 << (PC - 2);
            const bool ctl = (lane & MC) != 0;
            if constexpr (PT == 0) {        // swap (a0,a1) and (a2,a3)
                float t0 = a[0], t2 = a[2];
                a[0] = ctl ? a[1] : a[0];  a[1] = ctl ? t0 : a[1];
                a[2] = ctl ? a[3] : a[2];  a[3] = ctl ? t2 : a[3];
            } else {                        // PT == 1: swap (a0,a2),(a1,a3)
                float t0 = a[0], t1 = a[1];
                a[0] = ctl ? a[2] : a[0];  a[2] = ctl ? t0 : a[2];
                a[1] = ctl ? a[3] : a[1];  a[3] = ctl ? t1 : a[3];
            }
        } else {                            // both in-register
            if constexpr (PC == 1 && PT == 0) { float t = a[2]; a[2] = a[3]; a[3] = t; }
            else                              { float t = a[1]; a[1] = a[3]; a[3] = t; }
        }
    }
}

template<int C, int T>
__device__ __forceinline__ void cnot_w(float a[4], int lane) {
    cnot_p<6 - C, 6 - T>(a, lane);
}

template<int WA, int WB>
__device__ __forceinline__ void conv6(float a[4], int lane,
                                      const float2* __restrict__ cs, int base) {
    #pragma unroll
    for (int q = 0; q < 6; ++q) {
        ry_w<WA>(a, cs[base + 2 * q], lane);
        ry_w<WB>(a, cs[base + 2 * q + 1], lane);
        cnot_w<WA, WB>(a, lane);
    }
}

// ----------------------------- Kernel 1 ------------------------------
// 16 blocks x 256 threads; one warp per basis state, no per-gate barriers.
__global__ __launch_bounds__(256) void build_A_kernel(
        const float* __restrict__ QC1, const float* __restrict__ QC2,
        const float* __restrict__ QC3, const float* __restrict__ QP1,
        const float* __restrict__ QP2, const float* __restrict__ QP3,
        const float* __restrict__ QF) {
    __shared__ float2 cs[46];
    const int tid  = threadIdx.x;
    const int lane = tid & 31;
    const int basis = blockIdx.x * 8 + (tid >> 5);

    if (tid < 46) {
        float ang;
        if      (tid < 12) ang = QC1[tid];
        else if (tid < 24) ang = QC2[tid - 12];
        else if (tid < 36) ang = QC3[tid - 24];
        else if (tid == 36) ang =  QP1[0];
        else if (tid == 37) ang =  QP1[1];
        else if (tid == 38) ang = -QP1[1];
        else if (tid == 39) ang =  QP2[0];
        else if (tid == 40) ang =  QP2[1];
        else if (tid == 41) ang = -QP2[1];
        else if (tid == 42) ang =  QP3[0];
        else if (tid == 43) ang =  QP3[1];
        else if (tid == 44) ang = -QP3[1];
        else               ang = QF[0] + QF[1] + QF[2] + QF[3];  // RY angles add
        float sn, c;
        sincosf(0.5f * ang, &sn, &c);
        cs[tid] = make_float2(c, sn);
    }
    __syncthreads();   // the only barrier

    float a[4];
    #pragma unroll
    for (int r = 0; r < 4; ++r) a[r] = (lane * 4 + r == basis) ? 1.0f : 0.0f;

    // conv block 1: pairs (i, (i+1)%7)
    conv6<0,1>(a, lane, cs, 0);  conv6<1,2>(a, lane, cs, 0);
    conv6<2,3>(a, lane, cs, 0);  conv6<3,4>(a, lane, cs, 0);
    conv6<4,5>(a, lane, cs, 0);  conv6<5,6>(a, lane, cs, 0);
    conv6<6,0>(a, lane, cs, 0);
    // pool 1
    ry_w<0>(a, cs[36], lane); ry_w<3>(a, cs[37], lane);
    cnot_w<0,3>(a, lane);     ry_w<3>(a, cs[38], lane);
    ry_w<1>(a, cs[36], lane); ry_w<4>(a, cs[37], lane);
    cnot_w<1,4>(a, lane);     ry_w<4>(a, cs[38], lane);
    ry_w<2>(a, cs[36], lane); ry_w<5>(a, cs[37], lane);
    cnot_w<2,5>(a, lane);     ry_w<5>(a, cs[38], lane);
    // conv block 2
    conv6<3,4>(a, lane, cs, 12);
    conv6<4,5>(a, lane, cs, 12);
    conv6<5,6>(a, lane, cs, 12);
    #pragma unroll
    for (int q = 0; q < 6; ++q) {           // i == 6 special case
        ry_w<6>(a, cs[12 + 2 * q], lane);
        ry_w<3>(a, cs[13 + 2 * q], lane);
        cnot_w<6,0>(a, lane);
    }
    // pool 2
    ry_w<3>(a, cs[39], lane); ry_w<5>(a, cs[40], lane);
    cnot_w<3,5>(a, lane);     ry_w<5>(a, cs[41], lane);
    ry_w<4>(a, cs[39], lane); ry_w<6>(a, cs[40], lane);
    cnot_w<4,6>(a, lane);     ry_w<6>(a, cs[41], lane);
    // conv block 3 (reference bug preserved: CNOT(4,5))
    #pragma unroll
    for (int q = 0; q < 6; ++q) {
        ry_w<5>(a, cs[24 + 2 * q], lane);
        ry_w<6>(a, cs[25 + 2 * q], lane);
        cnot_w<4,5>(a, lane);
    }
    // pool 3 (reference bug preserved: CNOT(4,6))
    ry_w<5>(a, cs[42], lane); ry_w<6>(a, cs[43], lane);
    cnot_w<4,6>(a, lane);     ry_w<6>(a, cs[44], lane);
    // final: 4x RY(5) fused; CNOT(7,5)/CNOT(8,6) identity (ctrl |0>)
    ry_w<5>(a, cs[45], lane);
    cnot_w<5,6>(a, lane);
    cnot_w<6,5>(a, lane);

    reinterpret_cast<float4*>(g_AT)[basis * 32 + lane] =
        make_float4(a[0], a[1], a[2], a[3]);
}

// ----------------------------- Kernel 2 ------------------------------
// 256 blocks x 256 threads. Block = 16 batches, warp = 2 batches.
// Lane owns output rows m = 4*lane..4*lane+3 (component c == group k).
__device__ __forceinline__ void fma4(float4& acc, float xs, const float4& a) {
    acc.x = fmaf(xs, a.x, acc.x);
    acc.y = fmaf(xs, a.y, acc.y);
    acc.z = fmaf(xs, a.z, acc.z);
    acc.w = fmaf(xs, a.w, acc.w);
}

__global__ __launch_bounds__(256) void qcnn_apply_kernel(
        const float* __restrict__ X, float* __restrict__ out) {
    extern __shared__ float sm[];
    float4* As4 = reinterpret_cast<float4*>(sm);            // 4096 float4 [i][m]
    float4* Xs4 = reinterpret_cast<float4*>(sm + 16384);    // 512 float4

    const int tid  = threadIdx.x;
    const int warp = tid >> 5;
    const int lane = tid & 31;
    const int bbase = blockIdx.x * 16;

    const float4* gA4 = reinterpret_cast<const float4*>(g_AT);
    for (int k = tid; k < 4096; k += 256) As4[k] = gA4[k];
    const float4* gX4 = reinterpret_cast<const float4*>(X + (size_t)bbase * 128);
    for (int k = tid; k < 512; k += 256) Xs4[k] = gX4[k];
    __syncthreads();

    const int b0 = warp * 2;
    const float4* Xw = Xs4 + b0 * 32;

    float4 acc[2] = {{0,0,0,0},{0,0,0,0}};

    #pragma unroll 8
    for (int i4 = 0; i4 < 32; ++i4) {
        const float4 a0 = As4[i4 * 128 +       lane];
        const float4 a1 = As4[i4 * 128 +  32 + lane];
        const float4 a2 = As4[i4 * 128 +  64 + lane];
        const float4 a3 = As4[i4 * 128 +  96 + lane];
        #pragma unroll
        for (int g = 0; g < 2; ++g) {
            const float4 xv = Xw[g * 32 + i4];   // uniform address: broadcast
            fma4(acc[g], xv.x, a0);
            fma4(acc[g], xv.y, a1);
            fma4(acc[g], xv.z, a2);
            fma4(acc[g], xv.w, a3);
        }
    }

    #pragma unroll
    for (int g = 0; g < 2; ++g) {
        float q0 = acc[g].x * acc[g].x;
        float q1 = acc[g].y * acc[g].y;
        float q2 = acc[g].z * acc[g].z;
        float q3 = acc[g].w * acc[g].w;
        #pragma unroll
        for (int off = 16; off; off >>= 1) {
            q0 += __shfl_xor_sync(0xffffffffu, q0, off);
            q1 += __shfl_xor_sync(0xffffffffu, q1, off);
            q2 += __shfl_xor_sync(0xffffffffu, q2, off);
            q3 += __shfl_xor_sync(0xffffffffu, q3, off);
        }
        if (lane == 0) {
            const float S = q0 + q1 + q2 + q3;   // == ||x||^2 (U orthogonal)
            const float inv_s = 1.0f / S;
            const float p0 = q0 * inv_s, p1 = q1 * inv_s;
            const float p2 = q2 * inv_s, p3 = q3 * inv_s;
            const float mx = fmaxf(fmaxf(p0, p1), fmaxf(p2, p3));
            const float e0 = expf(p0 - mx), e1 = expf(p1 - mx);
            const float e2 = expf(p2 - mx), e3 = expf(p3 - mx);
            const float inv = 1.0f / (e0 + e1 + e2 + e3);
            reinterpret_cast<float4*>(out)[bbase + b0 + g] =
                make_float4(e0 * inv, e1 * inv, e2 * inv, e3 * inv);
        }
    }
}

// ----------------------------- launch --------------------------------
extern "C" void kernel_launch(void* const* d_in, const int* in_sizes, int n_in,
                              void* d_out, int out_size) {
    const float* x   = (const float*)d_in[0];
    const float* QC1 = (const float*)d_in[1];
    const float* QC2 = (const float*)d_in[2];
    const float* QC3 = (const float*)d_in[3];
    const float* QP1 = (const float*)d_in[4];
    const float* QP2 = (const float*)d_in[5];
    const float* QP3 = (const float*)d_in[6];
    const float* QF  = (const float*)d_in[7];

    const int B = in_sizes[0] / 128;

    build_A_kernel<<<16, 256>>>(QC1, QC2, QC3, QP1, QP2, QP3, QF);

    const int smem_bytes = (128 * 128 + 16 * 128) * sizeof(float);  // 72 KB
    cudaFuncSetAttribute(qcnn_apply_kernel,
                         cudaFuncAttributeMaxDynamicSharedMemorySize, smem_bytes);
    qcnn_apply_kernel<<<B / 16, 256, smem_bytes>>>(x, (float*)d_out);
}

// round 3
// speedup vs baseline: 1.9439x; 1.2262x over previous
#include <cuda_runtime.h>
#include <cuda_bf16.h>

// =====================================================================
// ATQCNN factorization:
//   U = fixed 128x128 orthogonal circuit matrix (wires 0..6; 7,8 inert)
//   Y[b] = U x[b];  q[b,k] = sum_{m&3==k} Y[b,m]^2;  out = softmax(q/sum q)
// Kernel 1: warp-per-basis register simulation (shfl, no barriers).
// Kernel 2: 4096x128x128 fp32 GEMM w/ squared-sum + softmax epilogue.
//           128 thr/block, warp = 4 batches, double-buffered A prefetch.
// =====================================================================

__device__ float g_AT[128 * 128];   // g_AT[i*128 + m] = <m| U |i>

// --------------------- gate primitives (register sim) -----------------
// Amp index m (7 bits): bits[6:2] = lane, bits[1:0] = register r.
// Bit position of wire w is P = 6 - w.

template<int P>
__device__ __forceinline__ void ry_p(float a[4], float c, float s, int lane) {
    if constexpr (P == 0) {                 // wire 6: pairs (a0,a1),(a2,a3)
        float n0 = c * a[0] - s * a[1];
        float n1 = fmaf(s, a[0], c * a[1]);
        float n2 = c * a[2] - s * a[3];
        float n3 = fmaf(s, a[2], c * a[3]);
        a[0] = n0; a[1] = n1; a[2] = n2; a[3] = n3;
    } else if constexpr (P == 1) {          // wire 5: pairs (a0,a2),(a1,a3)
        float n0 = c * a[0] - s * a[2];
        float n2 = fmaf(s, a[0], c * a[2]);
        float n1 = c * a[1] - s * a[3];
        float n3 = fmaf(s, a[1], c * a[3]);
        a[0] = n0; a[1] = n1; a[2] = n2; a[3] = n3;
    } else {                                // cross-lane wire
        constexpr int M = 1 << (P - 2);
        const float sgn = (lane & M) ? s : -s;
        #pragma unroll
        for (int r = 0; r < 4; ++r) {
            float pr = __shfl_xor_sync(0xffffffffu, a[r], M);
            a[r] = fmaf(sgn, pr, c * a[r]);
        }
    }
}

template<int W>
__device__ __forceinline__ void ry_w(float a[4], float2 cs, int lane) {
    ry_p<6 - W>(a, cs.x, cs.y, lane);
}

template<int PC, int PT>
__device__ __forceinline__ void cnot_p(float a[4], int lane) {
    if constexpr (PT >= 2) {                // target is a lane bit
        constexpr int MT = 1 << (PT - 2);
        if constexpr (PC >= 2) {            // control is a lane bit
            constexpr int MC = 1 << (PC - 2);
            const bool ctl = (lane & MC) != 0;
            #pragma unroll
            for (int r = 0; r < 4; ++r) {
                float pr = __shfl_xor_sync(0xffffffffu, a[r], MT);
                a[r] = ctl ? pr : a[r];
            }
        } else {                            // control in-register bit PC
            #pragma unroll
            for (int r = 0; r < 4; ++r) {
                if ((r >> PC) & 1) {        // compile-time constant after unroll
                    a[r] = __shfl_xor_sync(0xffffffffu, a[r], MT);
                }
            }
        }
    } else {                                // target in-register
        if constexpr (PC >= 2) {            // control is a lane bit
            constexpr int MC = 1 << (PC - 2);
            const bool ctl = (lane & MC) != 0;
            if constexpr (PT == 0) {        // swap (a0,a1) and (a2,a3)
                float t0 = a[0], t2 = a[2];
                a[0] = ctl ? a[1] : a[0];  a[1] = ctl ? t0 : a[1];
                a[2] = ctl ? a[3] : a[2];  a[3] = ctl ? t2 : a[3];
            } else {                        // PT == 1: swap (a0,a2),(a1,a3)
                float t0 = a[0], t1 = a[1];
                a[0] = ctl ? a[2] : a[0];  a[2] = ctl ? t0 : a[2];
                a[1] = ctl ? a[3] : a[1];  a[3] = ctl ? t1 : a[3];
            }
        } else {                            // both in-register
            if constexpr (PC == 1 && PT == 0) { float t = a[2]; a[2] = a[3]; a[3] = t; }
            else                              { float t = a[1]; a[1] = a[3]; a[3] = t; }
        }
    }
}

template<int C, int T>
__device__ __forceinline__ void cnot_w(float a[4], int lane) {
    cnot_p<6 - C, 6 - T>(a, lane);
}

template<int WA, int WB>
__device__ __forceinline__ void conv6(float a[4], int lane,
                                      const float2* __restrict__ cs, int base) {
    #pragma unroll
    for (int q = 0; q < 6; ++q) {
        ry_w<WA>(a, cs[base + 2 * q], lane);
        ry_w<WB>(a, cs[base + 2 * q + 1], lane);
        cnot_w<WA, WB>(a, lane);
    }
}

// ----------------------------- Kernel 1 ------------------------------
// 16 blocks x 256 threads; one warp per basis state, no per-gate barriers.
__global__ __launch_bounds__(256) void build_A_kernel(
        const float* __restrict__ QC1, const float* __restrict__ QC2,
        const float* __restrict__ QC3, const float* __restrict__ QP1,
        const float* __restrict__ QP2, const float* __restrict__ QP3,
        const float* __restrict__ QF) {
    __shared__ float2 cs[46];
    const int tid  = threadIdx.x;
    const int lane = tid & 31;
    const int basis = blockIdx.x * 8 + (tid >> 5);

    if (tid < 46) {
        float ang;
        if      (tid < 12) ang = QC1[tid];
        else if (tid < 24) ang = QC2[tid - 12];
        else if (tid < 36) ang = QC3[tid - 24];
        else if (tid == 36) ang =  QP1[0];
        else if (tid == 37) ang =  QP1[1];
        else if (tid == 38) ang = -QP1[1];
        else if (tid == 39) ang =  QP2[0];
        else if (tid == 40) ang =  QP2[1];
        else if (tid == 41) ang = -QP2[1];
        else if (tid == 42) ang =  QP3[0];
        else if (tid == 43) ang =  QP3[1];
        else if (tid == 44) ang = -QP3[1];
        else               ang = QF[0] + QF[1] + QF[2] + QF[3];  // RY angles add
        float sn, c;
        sincosf(0.5f * ang, &sn, &c);
        cs[tid] = make_float2(c, sn);
    }
    __syncthreads();   // the only barrier

    float a[4];
    #pragma unroll
    for (int r = 0; r < 4; ++r) a[r] = (lane * 4 + r == basis) ? 1.0f : 0.0f;

    // conv block 1: pairs (i, (i+1)%7)
    conv6<0,1>(a, lane, cs, 0);  conv6<1,2>(a, lane, cs, 0);
    conv6<2,3>(a, lane, cs, 0);  conv6<3,4>(a, lane, cs, 0);
    conv6<4,5>(a, lane, cs, 0);  conv6<5,6>(a, lane, cs, 0);
    conv6<6,0>(a, lane, cs, 0);
    // pool 1
    ry_w<0>(a, cs[36], lane); ry_w<3>(a, cs[37], lane);
    cnot_w<0,3>(a, lane);     ry_w<3>(a, cs[38], lane);
    ry_w<1>(a, cs[36], lane); ry_w<4>(a, cs[37], lane);
    cnot_w<1,4>(a, lane);     ry_w<4>(a, cs[38], lane);
    ry_w<2>(a, cs[36], lane); ry_w<5>(a, cs[37], lane);
    cnot_w<2,5>(a, lane);     ry_w<5>(a, cs[38], lane);
    // conv block 2
    conv6<3,4>(a, lane, cs, 12);
    conv6<4,5>(a, lane, cs, 12);
    conv6<5,6>(a, lane, cs, 12);
    #pragma unroll
    for (int q = 0; q < 6; ++q) {           // i == 6 special case
        ry_w<6>(a, cs[12 + 2 * q], lane);
        ry_w<3>(a, cs[13 + 2 * q], lane);
        cnot_w<6,0>(a, lane);
    }
    // pool 2
    ry_w<3>(a, cs[39], lane); ry_w<5>(a, cs[40], lane);
    cnot_w<3,5>(a, lane);     ry_w<5>(a, cs[41], lane);
    ry_w<4>(a, cs[39], lane); ry_w<6>(a, cs[40], lane);
    cnot_w<4,6>(a, lane);     ry_w<6>(a, cs[41], lane);
    // conv block 3 (reference bug preserved: CNOT(4,5))
    #pragma unroll
    for (int q = 0; q < 6; ++q) {
        ry_w<5>(a, cs[24 + 2 * q], lane);
        ry_w<6>(a, cs[25 + 2 * q], lane);
        cnot_w<4,5>(a, lane);
    }
    // pool 3 (reference bug preserved: CNOT(4,6))
    ry_w<5>(a, cs[42], lane); ry_w<6>(a, cs[43], lane);
    cnot_w<4,6>(a, lane);     ry_w<6>(a, cs[44], lane);
    // final: 4x RY(5) fused; CNOT(7,5)/CNOT(8,6) identity (ctrl |0>)
    ry_w<5>(a, cs[45], lane);
    cnot_w<5,6>(a, lane);
    cnot_w<6,5>(a, lane);

    reinterpret_cast<float4*>(g_AT)[basis * 32 + lane] =
        make_float4(a[0], a[1], a[2], a[3]);
}

// ----------------------------- Kernel 2 ------------------------------
// 256 blocks x 128 threads. Block = 16 batches, warp = 4 batches.
// Lane owns output rows m = 4*lane..4*lane+3 (component c == group k).
// A is double-buffered in registers (prefetch one i-group ahead).

#define APPLY_BATCH_PER_BLOCK 16
#define APPLY_THREADS 128
// Shared layout (in float4 units):
//   As4 : 33*128 float4 (32 i-groups + 1 pad group for the tail prefetch)
//   Xs4 : APPLY_BATCH_PER_BLOCK*32 float4
#define AS4_COUNT (33 * 128)
#define XS4_COUNT (APPLY_BATCH_PER_BLOCK * 32)

__device__ __forceinline__ void fma4(float4& acc, float xs, const float4& a) {
    acc.x = fmaf(xs, a.x, acc.x);
    acc.y = fmaf(xs, a.y, acc.y);
    acc.z = fmaf(xs, a.z, acc.z);
    acc.w = fmaf(xs, a.w, acc.w);
}

__global__ __launch_bounds__(APPLY_THREADS) void qcnn_apply_kernel(
        const float* __restrict__ X, float* __restrict__ out) {
    extern __shared__ float sm[];
    float4* As4 = reinterpret_cast<float4*>(sm);
    float4* Xs4 = reinterpret_cast<float4*>(sm) + AS4_COUNT;

    const int tid  = threadIdx.x;
    const int warp = tid >> 5;
    const int lane = tid & 31;
    const int bbase = blockIdx.x * APPLY_BATCH_PER_BLOCK;

    // Stage A^T (64 KB) and the X tile (8 KB), coalesced float4.
    const float4* gA4 = reinterpret_cast<const float4*>(g_AT);
    #pragma unroll
    for (int k = 0; k < 32; ++k) As4[tid + k * APPLY_THREADS] = gA4[tid + k * APPLY_THREADS];
    const float4* gX4 = reinterpret_cast<const float4*>(X + (size_t)bbase * 128);
    #pragma unroll
    for (int k = 0; k < XS4_COUNT / APPLY_THREADS; ++k)
        Xs4[tid + k * APPLY_THREADS] = gX4[tid + k * APPLY_THREADS];
    __syncthreads();

    const int b0 = warp * 4;                  // 4 batches per warp
    const float4* Xw = Xs4 + b0 * 32;
    const float4* Arow = As4 + lane;          // lane's 4 output columns

    float4 acc[4] = {{0,0,0,0},{0,0,0,0},{0,0,0,0},{0,0,0,0}};

    // Prime the pipeline: i-group 0.
    float4 c0 = Arow[0], c1 = Arow[32], c2 = Arow[64], c3 = Arow[96];

    #pragma unroll 4
    for (int i4 = 0; i4 < 32; ++i4) {
        // Prefetch next i-group (pad group for i4==31; values unused).
        const float4* An = Arow + (i4 + 1) * 128;
        float4 n0 = An[0], n1 = An[32], n2 = An[64], n3 = An[96];

        #pragma unroll
        for (int g = 0; g < 4; ++g) {
            const float4 xv = Xw[g * 32 + i4];   // uniform address: broadcast
            fma4(acc[g], xv.x, c0);
            fma4(acc[g], xv.y, c1);
            fma4(acc[g], xv.z, c2);
            fma4(acc[g], xv.w, c3);
        }
        c0 = n0; c1 = n1; c2 = n2; c3 = n3;
    }

    #pragma unroll
    for (int g = 0; g < 4; ++g) {
        float q0 = acc[g].x * acc[g].x;
        float q1 = acc[g].y * acc[g].y;
        float q2 = acc[g].z * acc[g].z;
        float q3 = acc[g].w * acc[g].w;
        #pragma unroll
        for (int off = 16; off; off >>= 1) {
            q0 += __shfl_xor_sync(0xffffffffu, q0, off);
            q1 += __shfl_xor_sync(0xffffffffu, q1, off);
            q2 += __shfl_xor_sync(0xffffffffu, q2, off);
            q3 += __shfl_xor_sync(0xffffffffu, q3, off);
        }
        if (lane == 0) {
            const float S = q0 + q1 + q2 + q3;   // == ||x||^2 (U orthogonal)
            const float inv_s = 1.0f / S;
            const float p0 = q0 * inv_s, p1 = q1 * inv_s;
            const float p2 = q2 * inv_s, p3 = q3 * inv_s;
            const float mx = fmaxf(fmaxf(p0, p1), fmaxf(p2, p3));
            const float e0 = expf(p0 - mx), e1 = expf(p1 - mx);
            const float e2 = expf(p2 - mx), e3 = expf(p3 - mx);
            const float inv = 1.0f / (e0 + e1 + e2 + e3);
            reinterpret_cast<float4*>(out)[bbase + b0 + g] =
                make_float4(e0 * inv, e1 * inv, e2 * inv, e3 * inv);
        }
    }
}

// ----------------------------- launch --------------------------------
extern "C" void kernel_launch(void* const* d_in, const int* in_sizes, int n_in,
                              void* d_out, int out_size) {
    const float* x   = (const float*)d_in[0];
    const float* QC1 = (const float*)d_in[1];
    const float* QC2 = (const float*)d_in[2];
    const float* QC3 = (const float*)d_in[3];
    const float* QP1 = (const float*)d_in[4];
    const float* QP2 = (const float*)d_in[5];
    const float* QP3 = (const float*)d_in[6];
    const float* QF  = (const float*)d_in[7];

    const int B = in_sizes[0] / 128;

    build_A_kernel<<<16, 256>>>(QC1, QC2, QC3, QP1, QP2, QP3, QF);

    const int smem_bytes = (AS4_COUNT + XS4_COUNT) * sizeof(float4);  // ~74 KB
    cudaFuncSetAttribute(qcnn_apply_kernel,
                         cudaFuncAttributeMaxDynamicSharedMemorySize, smem_bytes);
    qcnn_apply_kernel<<<B / APPLY_BATCH_PER_BLOCK, APPLY_THREADS, smem_bytes>>>(
        x, (float*)d_out);
}